// round 1
// baseline (speedup 1.0000x reference)
#include <cuda_runtime.h>

#define DD 160
#define HH 192
#define WW 224
#define VV (DD*HH*WW)      // 6881280
#define W4 (WW/4)          // 56
#define V4 (VV/4)          // 1720320

// Scratch: 5 fields (I, J, I2, J2, IJ), two ping-pong buffers (137.6 MB each)
__device__ float g_A[5u * VV];
__device__ float g_B[5u * VV];

__device__ __forceinline__ float4 f4add(float4 a, float4 b) {
    return make_float4(a.x+b.x, a.y+b.y, a.z+b.z, a.w+b.w);
}
__device__ __forceinline__ float4 f4sub(float4 a, float4 b) {
    return make_float4(a.x-b.x, a.y-b.y, a.z-b.z, a.w-b.w);
}

// ---------------------------------------------------------------------------
// Pass 1: along W (contiguous). Fuses computation of I2, J2, IJ.
// One block = 4 rows, blockDim (56, 4). Each thread produces 4 outputs (float4)
// per field via a sliding 9-tap window read from smem.
// ---------------------------------------------------------------------------
__global__ void __launch_bounds__(224) wpass(const float* __restrict__ I,
                                             const float* __restrict__ J) {
    __shared__ __align__(16) float sI[4][240];   // 4 zero pad + 224 + 4 zero pad (stride 240)
    __shared__ __align__(16) float sJ[4][240];
    const int tx = threadIdx.x;        // 0..55
    const int ty = threadIdx.y;        // 0..3
    const int row = blockIdx.x * 4 + ty;   // 0..30719 (d*H + h)
    const size_t rb = (size_t)row * W4;

    // Load row (vectorized) + zero pads
    float4 a = ((const float4*)I)[rb + tx];
    float4 b = ((const float4*)J)[rb + tx];
    ((float4*)(&sI[ty][4]))[tx] = a;
    ((float4*)(&sJ[ty][4]))[tx] = b;
    if (tx < 4) {
        sI[ty][tx] = 0.f;       sJ[ty][tx] = 0.f;
        sI[ty][228 + tx] = 0.f; sJ[ty][228 + tx] = 0.f;
    }
    __syncthreads();

    const int w0 = tx * 4;
    float ivv[12], jvv[12];
#pragma unroll
    for (int t = 0; t < 12; t++) {      // taps covering outputs w0..w0+3 (w0-4 .. w0+7)
        ivv[t] = sI[ty][w0 + t];        // smem index = (w0 - 4 + t) + 4
        jvv[t] = sJ[ty][w0 + t];
    }

    float oi[4], oj[4], oi2[4], oj2[4], oij[4];
    float si = 0.f, sj = 0.f, si2 = 0.f, sj2 = 0.f, sij = 0.f;
#pragma unroll
    for (int t = 0; t < 9; t++) {
        float x = ivv[t], y = jvv[t];
        si += x; sj += y; si2 += x*x; sj2 += y*y; sij += x*y;
    }
    oi[0]=si; oj[0]=sj; oi2[0]=si2; oj2[0]=sj2; oij[0]=sij;
#pragma unroll
    for (int k = 1; k < 4; k++) {
        float ia = ivv[k+8], ir = ivv[k-1];
        float ja = jvv[k+8], jr = jvv[k-1];
        si  += ia - ir;           sj  += ja - jr;
        si2 += ia*ia - ir*ir;     sj2 += ja*ja - jr*jr;
        sij += ia*ja - ir*jr;
        oi[k]=si; oj[k]=sj; oi2[k]=si2; oj2[k]=sj2; oij[k]=sij;
    }

    float4* A4 = (float4*)g_A;
    const size_t o = rb + tx;
    A4[o                  ] = make_float4(oi[0],  oi[1],  oi[2],  oi[3]);
    A4[o + (size_t)V4     ] = make_float4(oj[0],  oj[1],  oj[2],  oj[3]);
    A4[o + (size_t)V4 * 2 ] = make_float4(oi2[0], oi2[1], oi2[2], oi2[3]);
    A4[o + (size_t)V4 * 3 ] = make_float4(oj2[0], oj2[1], oj2[2], oj2[3]);
    A4[o + (size_t)V4 * 4 ] = make_float4(oij[0], oij[1], oij[2], oij[3]);
}

// ---------------------------------------------------------------------------
// Pass 2: along H. Block = one d-slice, 32-wide W chunk, full H=192.
// 5 fields processed sequentially through a 192x8 float4 smem tile.
// Each thread owns a 6-high segment of one float4 column -> running-window sum.
// ---------------------------------------------------------------------------
__global__ void __launch_bounds__(256) hpass() {
    __shared__ __align__(16) float4 s[HH * 9];   // stride 9 float4 per h row
    const int wc4 = blockIdx.x * 8;   // float4 column base (8 float4 = 32 floats)
    const int d   = blockIdx.y;
    const int tid = threadIdx.x;
    const float4* A4 = (const float4*)g_A;
    float4*       B4 = (float4*)g_B;
    const size_t base = (size_t)d * HH * W4 + wc4;

    const int c   = tid & 7;
    const int h0  = (tid >> 3) * 6;   // 32 segments * 6 = 192

    for (int f = 0; f < 5; f++) {
        const size_t fb = (size_t)f * V4 + base;
        for (int i = tid; i < HH * 8; i += 256) {
            int h = i >> 3, cc = i & 7;
            s[h * 9 + cc] = A4[fb + (size_t)h * W4 + cc];
        }
        __syncthreads();

        float4 sum = make_float4(0.f, 0.f, 0.f, 0.f);
#pragma unroll
        for (int k = -4; k <= 4; k++) {
            int hh = h0 + k;
            if (hh >= 0 && hh < HH) sum = f4add(sum, s[hh * 9 + c]);
        }
        B4[fb + (size_t)h0 * W4 + c] = sum;
#pragma unroll
        for (int k = 1; k < 6; k++) {
            int ha = h0 + k + 4, hs = h0 + k - 5;
            if (ha < HH)  sum = f4add(sum, s[ha * 9 + c]);
            if (hs >= 0)  sum = f4sub(sum, s[hs * 9 + c]);
            B4[fb + (size_t)(h0 + k) * W4 + c] = sum;
        }
        __syncthreads();
    }
}

// ---------------------------------------------------------------------------
// Pass 3: along D, fused with cc computation and global mean reduction.
// Block = one h row, 32-wide W chunk, 32-deep D chunk (with 4-halo in smem).
// All 5 fields resident in smem simultaneously so cc is computed in-place.
// ---------------------------------------------------------------------------
__device__ __forceinline__ float cc1(float si, float sj, float si2, float sj2, float sij) {
    const float inv = 1.0f / 729.0f;
    float cross = sij - si * sj * inv;
    float ivar  = si2 - si * si * inv;
    float jvar  = sj2 - sj * sj * inv;
    return (cross * cross) / (ivar * jvar + 1e-5f);
}

__global__ void __launch_bounds__(256) dpass(float* __restrict__ out) {
    __shared__ __align__(16) float4 s[5][40 * 9];   // 40 = 32 + 2*4 halo
    __shared__ float red[256];
    const int wc4 = blockIdx.x * 8;
    const int h   = blockIdx.y;
    const int d0  = blockIdx.z * 32;
    const int tid = threadIdx.x;
    const float4* B4 = (const float4*)g_B;
    const size_t base = (size_t)h * W4 + wc4;

#pragma unroll
    for (int f = 0; f < 5; f++) {
        const size_t fb = (size_t)f * V4 + base;
        for (int i = tid; i < 40 * 8; i += 256) {
            int r = i >> 3, c = i & 7;
            int dg = d0 - 4 + r;
            float4 v = make_float4(0.f, 0.f, 0.f, 0.f);
            if (dg >= 0 && dg < DD) v = B4[fb + (size_t)dg * (HH * W4) + c];
            s[f][r * 9 + c] = v;
        }
    }
    __syncthreads();

    const int c  = tid & 7;
    const int dd = tid >> 3;   // 0..31, output d = d0 + dd, taps at local rows dd..dd+8
    float4 z = make_float4(0.f, 0.f, 0.f, 0.f);
    float4 sI = z, sJ = z, sI2 = z, sJ2 = z, sIJ = z;
#pragma unroll
    for (int t = 0; t < 9; t++) {
        int r = (dd + t) * 9 + c;
        sI  = f4add(sI,  s[0][r]);
        sJ  = f4add(sJ,  s[1][r]);
        sI2 = f4add(sI2, s[2][r]);
        sJ2 = f4add(sJ2, s[3][r]);
        sIJ = f4add(sIJ, s[4][r]);
    }

    float part = 0.f;
    part += cc1(sI.x, sJ.x, sI2.x, sJ2.x, sIJ.x);
    part += cc1(sI.y, sJ.y, sI2.y, sJ2.y, sIJ.y);
    part += cc1(sI.z, sJ.z, sI2.z, sJ2.z, sIJ.z);
    part += cc1(sI.w, sJ.w, sI2.w, sJ2.w, sIJ.w);

    red[tid] = part;
    __syncthreads();
#pragma unroll
    for (int stride = 128; stride > 0; stride >>= 1) {
        if (tid < stride) red[tid] += red[tid + stride];
        __syncthreads();
    }
    if (tid == 0) {
        atomicAdd(out, -red[0] * (1.0f / (float)VV));
    }
}

__global__ void zout(float* out) { out[0] = 0.f; }

// ---------------------------------------------------------------------------
extern "C" void kernel_launch(void* const* d_in, const int* in_sizes, int n_in,
                              void* d_out, int out_size) {
    const float* I = (const float*)d_in[0];
    const float* J = (const float*)d_in[1];
    float* out = (float*)d_out;

    zout<<<1, 1>>>(out);
    wpass<<<7680, dim3(56, 4)>>>(I, J);          // 30720 rows / 4
    hpass<<<dim3(7, 160), 256>>>();              // 7 W-chunks x 160 d
    dpass<<<dim3(7, 192, 5), 256>>>(out);        // 7 W-chunks x 192 h x 5 D-chunks
}

// round 2
// speedup vs baseline: 1.6349x; 1.6349x over previous
#include <cuda_runtime.h>
#include <cuda_fp16.h>

#define DD 160
#define HH 192
#define WW 224
#define VV (DD*HH*WW)        // 6881280
#define W4 (WW/4)            // 56 (float4 per row, wpass input)
#define VU2 (VV/4)           // uint2 (4-half) elems per field
#define VH2 (VV/2)           // half2 elems per field
#define PL  (HH*WW/2)        // half2 per d-plane = 21504

// fp16 scratch: 5 fields x VV halves, two buffers (68.8 MB each)
__device__ __half g_A[5u * VV];
__device__ __half g_B[5u * VV];

// ---- helpers ---------------------------------------------------------------
union U2H4 { uint2 u; __half2 h[2]; };

__device__ __forceinline__ float4 u2_to_f4(uint2 u) {
    U2H4 t; t.u = u;
    float2 a = __half22float2(t.h[0]);
    float2 b = __half22float2(t.h[1]);
    return make_float4(a.x, a.y, b.x, b.y);
}
__device__ __forceinline__ uint2 f4_to_u2(float4 v) {
    U2H4 t;
    t.h[0] = __floats2half2_rn(v.x, v.y);
    t.h[1] = __floats2half2_rn(v.z, v.w);
    return t.u;
}
__device__ __forceinline__ void st4h(__half* p, float a, float b, float c, float d) {
    U2H4 t;
    t.h[0] = __floats2half2_rn(a, b);
    t.h[1] = __floats2half2_rn(c, d);
    *(uint2*)p = t.u;
}
__device__ __forceinline__ float4 f4add(float4 a, float4 b) {
    return make_float4(a.x+b.x, a.y+b.y, a.z+b.z, a.w+b.w);
}
__device__ __forceinline__ float4 f4sub(float4 a, float4 b) {
    return make_float4(a.x-b.x, a.y-b.y, a.z-b.z, a.w-b.w);
}

// ---------------------------------------------------------------------------
// Pass 1: along W (contiguous). fp32 in, 5 fp16 W-summed fields out.
// Block = 4 rows, blockDim (56,4), 4 outputs/thread/field via sliding window.
// ---------------------------------------------------------------------------
__global__ void __launch_bounds__(224) wpass(const float* __restrict__ I,
                                             const float* __restrict__ J) {
    __shared__ __align__(16) float sI[4][240];   // 4 pad + 224 + 4 pad
    __shared__ __align__(16) float sJ[4][240];
    const int tx = threadIdx.x;             // 0..55
    const int ty = threadIdx.y;             // 0..3
    const int row = blockIdx.x * 4 + ty;    // d*H + h
    const size_t rb = (size_t)row * W4;

    float4 a = ((const float4*)I)[rb + tx];
    float4 b = ((const float4*)J)[rb + tx];
    ((float4*)(&sI[ty][4]))[tx] = a;
    ((float4*)(&sJ[ty][4]))[tx] = b;
    if (tx < 4) {
        sI[ty][tx] = 0.f;       sJ[ty][tx] = 0.f;
        sI[ty][228 + tx] = 0.f; sJ[ty][228 + tx] = 0.f;
    }
    __syncthreads();

    const int w0 = tx * 4;
    float iv[12], jv[12];
#pragma unroll
    for (int t = 0; t < 12; t++) { iv[t] = sI[ty][w0 + t]; jv[t] = sJ[ty][w0 + t]; }

    float oi[4], oj[4], oi2[4], oj2[4], oij[4];
    float si=0.f, sj=0.f, si2=0.f, sj2=0.f, sij=0.f;
#pragma unroll
    for (int t = 0; t < 9; t++) {
        float x = iv[t], y = jv[t];
        si += x; sj += y; si2 += x*x; sj2 += y*y; sij += x*y;
    }
    oi[0]=si; oj[0]=sj; oi2[0]=si2; oj2[0]=sj2; oij[0]=sij;
#pragma unroll
    for (int k = 1; k < 4; k++) {
        float ia = iv[k+8], ir = iv[k-1];
        float ja = jv[k+8], jr = jv[k-1];
        si  += ia - ir;        sj  += ja - jr;
        si2 += ia*ia - ir*ir;  sj2 += ja*ja - jr*jr;
        sij += ia*ja - ir*jr;
        oi[k]=si; oj[k]=sj; oi2[k]=si2; oj2[k]=sj2; oij[k]=sij;
    }

    const size_t o = (size_t)row * WW + w0;      // half element offset
    st4h(g_A + 0u*VV + o, oi[0],  oi[1],  oi[2],  oi[3]);
    st4h(g_A + 1u*VV + o, oj[0],  oj[1],  oj[2],  oj[3]);
    st4h(g_A + 2u*VV + o, oi2[0], oi2[1], oi2[2], oi2[3]);
    st4h(g_A + 3u*VV + o, oj2[0], oj2[1], oj2[2], oj2[3]);
    st4h(g_A + 4u*VV + o, oij[0], oij[1], oij[2], oij[3]);
}

// ---------------------------------------------------------------------------
// Pass 2: along H. fp16 in/out. Block = one d-slice, 32-half W chunk, full H.
// 8B (4-half) vectors; each thread owns a 6-high segment, running window.
// ---------------------------------------------------------------------------
__global__ void __launch_bounds__(256) hpass() {
    __shared__ __align__(16) uint2 s[HH * 9];    // stride 9 uint2 per h row
    const int wc = blockIdx.x * 8;               // uint2 column base (8 u2 = 32 halfs)
    const int d  = blockIdx.y;
    const int tid = threadIdx.x;
    const uint2* A2 = (const uint2*)g_A;
    uint2*       B2 = (uint2*)g_B;
    const size_t base = (size_t)d * (HH * (WW/4)) + wc;   // WW/4 = 56 u2 per row

    const int c  = tid & 7;
    const int h0 = (tid >> 3) * 6;               // 32 segments * 6 = 192

    for (int f = 0; f < 5; f++) {
        const size_t fb = (size_t)f * VU2 + base;
        for (int i = tid; i < HH * 8; i += 256) {
            int h = i >> 3, cc = i & 7;
            s[h * 9 + cc] = A2[fb + (size_t)h * (WW/4) + cc];
        }
        __syncthreads();

        float4 sum = make_float4(0.f, 0.f, 0.f, 0.f);
#pragma unroll
        for (int k = -4; k <= 4; k++) {
            int hh = h0 + k;
            if (hh >= 0 && hh < HH) sum = f4add(sum, u2_to_f4(s[hh * 9 + c]));
        }
        B2[fb + (size_t)h0 * (WW/4) + c] = f4_to_u2(sum);
#pragma unroll
        for (int k = 1; k < 6; k++) {
            int ha = h0 + k + 4, hs = h0 + k - 5;
            if (ha < HH)  sum = f4add(sum, u2_to_f4(s[ha * 9 + c]));
            if (hs >= 0)  sum = f4sub(sum, u2_to_f4(s[hs * 9 + c]));
            B2[fb + (size_t)(h0 + k) * (WW/4) + c] = f4_to_u2(sum);
        }
        __syncthreads();
    }
}

// ---------------------------------------------------------------------------
// Pass 3: along D, streaming running-window in registers. No smem taps.
// Thread = one half2 column (h,w), 40-deep D chunk. Fused cc + reduction.
// ---------------------------------------------------------------------------
__device__ __forceinline__ float cc1(float si, float sj, float si2, float sj2, float sij) {
    const float inv = 1.0f / 729.0f;
    float cross = sij - si * sj * inv;
    float ivar  = si2 - si * si * inv;
    float jvar  = sj2 - sj * sj * inv;
    return __fdividef(cross * cross, ivar * jvar + 1e-5f);
}

__global__ void __launch_bounds__(256) dpass(float* __restrict__ out) {
    const int tid = threadIdx.x;
    const int col = blockIdx.x * 256 + tid;      // 0..21503 (h*112 + w2)
    const int d0  = blockIdx.y * 40;
    const __half2* B = (const __half2*)g_B;

    float2 sI={0.f,0.f}, sJ={0.f,0.f}, sI2={0.f,0.f}, sJ2={0.f,0.f}, sIJ={0.f,0.f};

#define ACC5(q, OP) { \
    float2 v0 = __half22float2(B[0u*VH2 + (q)]); \
    float2 v1 = __half22float2(B[1u*VH2 + (q)]); \
    float2 v2 = __half22float2(B[2u*VH2 + (q)]); \
    float2 v3 = __half22float2(B[3u*VH2 + (q)]); \
    float2 v4 = __half22float2(B[4u*VH2 + (q)]); \
    sI.x  OP v0.x; sI.y  OP v0.y;  sJ.x  OP v1.x; sJ.y  OP v1.y; \
    sI2.x OP v2.x; sI2.y OP v2.y;  sJ2.x OP v3.x; sJ2.y OP v3.y; \
    sIJ.x OP v4.x; sIJ.y OP v4.y; }

#pragma unroll
    for (int t = -4; t <= 4; t++) {
        int dt = d0 + t;
        if (dt >= 0 && dt < DD) {
            size_t q = (size_t)dt * PL + col;
            ACC5(q, +=);
        }
    }

    float acc = 0.f;
#pragma unroll 5
    for (int dd = 0; dd < 40; dd++) {
        acc += cc1(sI.x, sJ.x, sI2.x, sJ2.x, sIJ.x);
        acc += cc1(sI.y, sJ.y, sI2.y, sJ2.y, sIJ.y);
        int d = d0 + dd;
        int ta = d + 5, ts = d - 4;
        if (ta < DD) { size_t q = (size_t)ta * PL + col; ACC5(q, +=); }
        if (ts >= 0) { size_t q = (size_t)ts * PL + col; ACC5(q, -=); }
    }
#undef ACC5

    // block reduction
#pragma unroll
    for (int o = 16; o > 0; o >>= 1) acc += __shfl_xor_sync(0xFFFFFFFFu, acc, o);
    __shared__ float wsum[8];
    if ((tid & 31) == 0) wsum[tid >> 5] = acc;
    __syncthreads();
    if (tid == 0) {
        float s = 0.f;
#pragma unroll
        for (int i = 0; i < 8; i++) s += wsum[i];
        atomicAdd(out, -s * (1.0f / (float)VV));
    }
}

__global__ void zout(float* out) { out[0] = 0.f; }

// ---------------------------------------------------------------------------
extern "C" void kernel_launch(void* const* d_in, const int* in_sizes, int n_in,
                              void* d_out, int out_size) {
    const float* I = (const float*)d_in[0];
    const float* J = (const float*)d_in[1];
    float* out = (float*)d_out;

    zout<<<1, 1>>>(out);
    wpass<<<7680, dim3(56, 4)>>>(I, J);      // 30720 rows / 4
    hpass<<<dim3(7, 160), 256>>>();          // 7 W-chunks x 160 d
    dpass<<<dim3(84, 4), 256>>>(out);        // 21504 cols / 256, 4 D-chunks
}

// round 3
// speedup vs baseline: 1.7433x; 1.0663x over previous
#include <cuda_runtime.h>
#include <cuda_fp16.h>

#define DD 160
#define HH 192
#define WW 224
#define VV (DD*HH*WW)        // 6881280
#define W4 (WW/4)            // 56 float4 per row (wpass input)
#define WU2 (WW/4)           // 56 uint2 (4-half) per row
#define VU2 (VV/4)           // uint2 elems per field
#define VH2 (VV/2)           // half2 elems per field
#define PL  (HH*WW/2)        // half2 per d-plane = 21504

// fp16 scratch: 5 fields x VV halves, two buffers (68.8 MB each)
__device__ __half g_A[5u * VV];
__device__ __half g_B[5u * VV];

// ---- helpers ---------------------------------------------------------------
union U2H4 { uint2 u; __half2 h[2]; };

__device__ __forceinline__ float4 u2_to_f4(uint2 u) {
    U2H4 t; t.u = u;
    float2 a = __half22float2(t.h[0]);
    float2 b = __half22float2(t.h[1]);
    return make_float4(a.x, a.y, b.x, b.y);
}
__device__ __forceinline__ uint2 f4_to_u2(float4 v) {
    U2H4 t;
    t.h[0] = __floats2half2_rn(v.x, v.y);
    t.h[1] = __floats2half2_rn(v.z, v.w);
    return t.u;
}
__device__ __forceinline__ void st4h(__half* p, float a, float b, float c, float d) {
    U2H4 t;
    t.h[0] = __floats2half2_rn(a, b);
    t.h[1] = __floats2half2_rn(c, d);
    *(uint2*)p = t.u;
}

// ---------------------------------------------------------------------------
// Pass 1: along W (contiguous). fp32 in, 5 fp16 W-summed fields out.
// ---------------------------------------------------------------------------
__global__ void __launch_bounds__(224) wpass(const float* __restrict__ I,
                                             const float* __restrict__ J) {
    __shared__ __align__(16) float sI[4][240];   // 4 pad + 224 + 4 pad
    __shared__ __align__(16) float sJ[4][240];
    const int tx = threadIdx.x;             // 0..55
    const int ty = threadIdx.y;             // 0..3
    const int row = blockIdx.x * 4 + ty;    // d*H + h
    const size_t rb = (size_t)row * W4;

    float4 a = ((const float4*)I)[rb + tx];
    float4 b = ((const float4*)J)[rb + tx];
    ((float4*)(&sI[ty][4]))[tx] = a;
    ((float4*)(&sJ[ty][4]))[tx] = b;
    if (tx < 4) {
        sI[ty][tx] = 0.f;       sJ[ty][tx] = 0.f;
        sI[ty][228 + tx] = 0.f; sJ[ty][228 + tx] = 0.f;
    }
    __syncthreads();

    const int w0 = tx * 4;
    float iv[12], jv[12];
#pragma unroll
    for (int t = 0; t < 12; t++) { iv[t] = sI[ty][w0 + t]; jv[t] = sJ[ty][w0 + t]; }

    float oi[4], oj[4], oi2[4], oj2[4], oij[4];
    float si=0.f, sj=0.f, si2=0.f, sj2=0.f, sij=0.f;
#pragma unroll
    for (int t = 0; t < 9; t++) {
        float x = iv[t], y = jv[t];
        si += x; sj += y; si2 += x*x; sj2 += y*y; sij += x*y;
    }
    oi[0]=si; oj[0]=sj; oi2[0]=si2; oj2[0]=sj2; oij[0]=sij;
#pragma unroll
    for (int k = 1; k < 4; k++) {
        float ia = iv[k+8], ir = iv[k-1];
        float ja = jv[k+8], jr = jv[k-1];
        si  += ia - ir;        sj  += ja - jr;
        si2 += ia*ia - ir*ir;  sj2 += ja*ja - jr*jr;
        sij += ia*ja - ir*jr;
        oi[k]=si; oj[k]=sj; oi2[k]=si2; oj2[k]=sj2; oij[k]=sij;
    }

    const size_t o = (size_t)row * WW + w0;      // half element offset
    st4h(g_A + 0u*VV + o, oi[0],  oi[1],  oi[2],  oi[3]);
    st4h(g_A + 1u*VV + o, oj[0],  oj[1],  oj[2],  oj[3]);
    st4h(g_A + 2u*VV + o, oi2[0], oi2[1], oi2[2], oi2[3]);
    st4h(g_A + 3u*VV + o, oj2[0], oj2[1], oj2[2], oj2[3]);
    st4h(g_A + 4u*VV + o, oij[0], oij[1], oij[2], oij[3]);
}

// ---------------------------------------------------------------------------
// Pass 2: along H, register-streaming running window (no smem, no barriers).
// Thread = one uint2 column (4 halfs, fixed d,w4) for one field, 48-high chunk.
// ---------------------------------------------------------------------------
__global__ void __launch_bounds__(256) hpass() {
    const int tid = threadIdx.x;
    const int col = blockIdx.x * 256 + tid;       // 0..8959 (d*56 + w4)
    const int f   = blockIdx.y;
    const int h0  = blockIdx.z * 48;
    const int d   = col / WU2;
    const int w4  = col - d * WU2;

    const uint2* A2 = (const uint2*)g_A + (size_t)f * VU2
                    + (size_t)d * (HH * WU2) + w4;
    uint2*       B2 = (uint2*)g_B + (size_t)f * VU2
                    + (size_t)d * (HH * WU2) + w4;

    float4 s = make_float4(0.f, 0.f, 0.f, 0.f);
#pragma unroll
    for (int t = -4; t <= 4; t++) {
        int h = h0 + t;                           // h0+4 <= 148 < 192 always
        if (h >= 0) {
            float4 v = u2_to_f4(A2[(size_t)h * WU2]);
            s.x += v.x; s.y += v.y; s.z += v.z; s.w += v.w;
        }
    }
#pragma unroll 4
    for (int k = 0; k < 48; k++) {
        const int h = h0 + k;
        B2[(size_t)h * WU2] = f4_to_u2(s);
        int ha = h + 5, hs = h - 4;
        if (ha < HH) {
            float4 v = u2_to_f4(A2[(size_t)ha * WU2]);
            s.x += v.x; s.y += v.y; s.z += v.z; s.w += v.w;
        }
        if (hs >= 0) {
            float4 v = u2_to_f4(A2[(size_t)hs * WU2]);
            s.x -= v.x; s.y -= v.y; s.z -= v.z; s.w -= v.w;
        }
    }
}

// ---------------------------------------------------------------------------
// Pass 3: along D, streaming running window in registers + fused cc/reduction.
// Thread = one half2 column (h,w2), 16-deep D chunk (10 chunks -> 840 blocks).
// ---------------------------------------------------------------------------
__device__ __forceinline__ float cc1(float si, float sj, float si2, float sj2, float sij) {
    const float inv = 1.0f / 729.0f;
    float cross = sij - si * sj * inv;
    float ivar  = si2 - si * si * inv;
    float jvar  = sj2 - sj * sj * inv;
    return __fdividef(cross * cross, ivar * jvar + 1e-5f);
}

__global__ void __launch_bounds__(256) dpass(float* __restrict__ out) {
    const int tid = threadIdx.x;
    const int col = blockIdx.x * 256 + tid;      // 0..21503 (h*112 + w2)
    const int d0  = blockIdx.y * 16;
    const __half2* B = (const __half2*)g_B;

    float2 sI={0.f,0.f}, sJ={0.f,0.f}, sI2={0.f,0.f}, sJ2={0.f,0.f}, sIJ={0.f,0.f};

#define ACC5(q, OP) { \
    float2 v0 = __half22float2(B[0u*VH2 + (q)]); \
    float2 v1 = __half22float2(B[1u*VH2 + (q)]); \
    float2 v2 = __half22float2(B[2u*VH2 + (q)]); \
    float2 v3 = __half22float2(B[3u*VH2 + (q)]); \
    float2 v4 = __half22float2(B[4u*VH2 + (q)]); \
    sI.x  OP v0.x; sI.y  OP v0.y;  sJ.x  OP v1.x; sJ.y  OP v1.y; \
    sI2.x OP v2.x; sI2.y OP v2.y;  sJ2.x OP v3.x; sJ2.y OP v3.y; \
    sIJ.x OP v4.x; sIJ.y OP v4.y; }

#pragma unroll
    for (int t = -4; t <= 4; t++) {
        int dt = d0 + t;                          // d0+4 <= 148 < 160 always
        if (dt >= 0) {
            size_t q = (size_t)dt * PL + col;
            ACC5(q, +=);
        }
    }

    float acc = 0.f;
#pragma unroll 4
    for (int dd = 0; dd < 16; dd++) {
        acc += cc1(sI.x, sJ.x, sI2.x, sJ2.x, sIJ.x);
        acc += cc1(sI.y, sJ.y, sI2.y, sJ2.y, sIJ.y);
        int d = d0 + dd;
        int ta = d + 5, ts = d - 4;
        if (ta < DD) { size_t q = (size_t)ta * PL + col; ACC5(q, +=); }
        if (ts >= 0) { size_t q = (size_t)ts * PL + col; ACC5(q, -=); }
    }
#undef ACC5

    // block reduction
#pragma unroll
    for (int o = 16; o > 0; o >>= 1) acc += __shfl_xor_sync(0xFFFFFFFFu, acc, o);
    __shared__ float wsum[8];
    if ((tid & 31) == 0) wsum[tid >> 5] = acc;
    __syncthreads();
    if (tid == 0) {
        float s = 0.f;
#pragma unroll
        for (int i = 0; i < 8; i++) s += wsum[i];
        atomicAdd(out, -s * (1.0f / (float)VV));
    }
}

__global__ void zout(float* out) { out[0] = 0.f; }

// ---------------------------------------------------------------------------
extern "C" void kernel_launch(void* const* d_in, const int* in_sizes, int n_in,
                              void* d_out, int out_size) {
    const float* I = (const float*)d_in[0];
    const float* J = (const float*)d_in[1];
    float* out = (float*)d_out;

    zout<<<1, 1>>>(out);
    wpass<<<7680, dim3(56, 4)>>>(I, J);        // 30720 rows / 4
    hpass<<<dim3(35, 5, 4), 256>>>();          // 8960 cols, 5 fields, 4 H-chunks
    dpass<<<dim3(84, 10), 256>>>(out);         // 21504 cols / 256, 10 D-chunks
}

// round 4
// speedup vs baseline: 2.0196x; 1.1585x over previous
#include <cuda_runtime.h>
#include <cuda_fp16.h>

#define DD 160
#define HH 192
#define WW 224
#define VV (DD*HH*WW)        // 6881280
#define W4 (WW/4)            // 56 float4 per row (wpass input)
#define WU2 (WW/4)           // 56 uint2 (4-half) per row
#define VU2 (VV/4)           // uint2 elems per field
#define PL2 (HH*WW/4)        // uint2 per d-plane = 10752

// fp16 scratch: 5 fields x VV halves, two buffers (68.8 MB each)
__device__ __half g_A[5u * VV];
__device__ __half g_B[5u * VV];

// ---- helpers ---------------------------------------------------------------
union U2H4 { uint2 u; __half2 h[2]; };

__device__ __forceinline__ void st4h(__half* p, float a, float b, float c, float d) {
    U2H4 t;
    t.h[0] = __floats2half2_rn(a, b);
    t.h[1] = __floats2half2_rn(c, d);
    *(uint2*)p = t.u;
}

// ---------------------------------------------------------------------------
// Pass 1: along W (contiguous). fp32 in, 5 fp16 W-summed fields out.
// ---------------------------------------------------------------------------
__global__ void __launch_bounds__(224) wpass(const float* __restrict__ I,
                                             const float* __restrict__ J,
                                             float* __restrict__ out) {
    __shared__ __align__(16) float sI[4][240];   // 4 pad + 224 + 4 pad
    __shared__ __align__(16) float sJ[4][240];
    const int tx = threadIdx.x;             // 0..55
    const int ty = threadIdx.y;             // 0..3
    if (blockIdx.x == 0 && tx == 0 && ty == 0) out[0] = 0.f;  // init accumulator
    const int row = blockIdx.x * 4 + ty;    // d*H + h
    const size_t rb = (size_t)row * W4;

    float4 a = ((const float4*)I)[rb + tx];
    float4 b = ((const float4*)J)[rb + tx];
    ((float4*)(&sI[ty][4]))[tx] = a;
    ((float4*)(&sJ[ty][4]))[tx] = b;
    if (tx < 4) {
        sI[ty][tx] = 0.f;       sJ[ty][tx] = 0.f;
        sI[ty][228 + tx] = 0.f; sJ[ty][228 + tx] = 0.f;
    }
    __syncthreads();

    const int w0 = tx * 4;
    float iv[12], jv[12];
#pragma unroll
    for (int t = 0; t < 12; t++) { iv[t] = sI[ty][w0 + t]; jv[t] = sJ[ty][w0 + t]; }

    float oi[4], oj[4], oi2[4], oj2[4], oij[4];
    float si=0.f, sj=0.f, si2=0.f, sj2=0.f, sij=0.f;
#pragma unroll
    for (int t = 0; t < 9; t++) {
        float x = iv[t], y = jv[t];
        si += x; sj += y; si2 += x*x; sj2 += y*y; sij += x*y;
    }
    oi[0]=si; oj[0]=sj; oi2[0]=si2; oj2[0]=sj2; oij[0]=sij;
#pragma unroll
    for (int k = 1; k < 4; k++) {
        float ia = iv[k+8], ir = iv[k-1];
        float ja = jv[k+8], jr = jv[k-1];
        si  += ia - ir;        sj  += ja - jr;
        si2 += ia*ia - ir*ir;  sj2 += ja*ja - jr*jr;
        sij += ia*ja - ir*jr;
        oi[k]=si; oj[k]=sj; oi2[k]=si2; oj2[k]=sj2; oij[k]=sij;
    }

    const size_t o = (size_t)row * WW + w0;      // half element offset
    st4h(g_A + 0u*VV + o, oi[0],  oi[1],  oi[2],  oi[3]);
    st4h(g_A + 1u*VV + o, oj[0],  oj[1],  oj[2],  oj[3]);
    st4h(g_A + 2u*VV + o, oi2[0], oi2[1], oi2[2], oi2[3]);
    st4h(g_A + 3u*VV + o, oj2[0], oj2[1], oj2[2], oj2[3]);
    st4h(g_A + 4u*VV + o, oij[0], oij[1], oij[2], oij[3]);
}

// ---------------------------------------------------------------------------
// Pass 2: along H. fp16 running-window accumulators (HADD2/HSUB2), no
// converts, no smem. Thread = one uint2 column (4 halves) of one field.
// ---------------------------------------------------------------------------
__global__ void __launch_bounds__(256) hpass() {
    const int tid = threadIdx.x;
    const int col = blockIdx.x * 256 + tid;       // 0..8959 (d*56 + w4)
    const int f   = blockIdx.y;
    const int h0  = blockIdx.z * 24;
    const int d   = col / WU2;
    const int w4  = col - d * WU2;

    const uint2* A2 = (const uint2*)g_A + (size_t)f * VU2
                    + (size_t)d * (HH * WU2) + w4;
    uint2*       B2 = (uint2*)g_B + (size_t)f * VU2
                    + (size_t)d * (HH * WU2) + w4;

    __half2 s0 = __float2half2_rn(0.f), s1 = s0;
#pragma unroll
    for (int t = -4; t <= 4; t++) {
        int h = h0 + t;                           // h0+4 <= 172 < 192 always
        if (h >= 0) {
            U2H4 v; v.u = A2[(size_t)h * WU2];
            s0 = __hadd2(s0, v.h[0]); s1 = __hadd2(s1, v.h[1]);
        }
    }
#pragma unroll 6
    for (int k = 0; k < 24; k++) {
        const int h = h0 + k;
        U2H4 o; o.h[0] = s0; o.h[1] = s1;
        B2[(size_t)h * WU2] = o.u;
        int ha = h + 5, hs = h - 4;
        if (ha < HH) {
            U2H4 v; v.u = A2[(size_t)ha * WU2];
            s0 = __hadd2(s0, v.h[0]); s1 = __hadd2(s1, v.h[1]);
        }
        if (hs >= 0) {
            U2H4 v; v.u = A2[(size_t)hs * WU2];
            s0 = __hsub2(s0, v.h[0]); s1 = __hsub2(s1, v.h[1]);
        }
    }
}

// ---------------------------------------------------------------------------
// Pass 3: along D. fp16 running-window accumulators; fp32 only at cc time.
// Thread = one uint2 column (4 halves, all 5 fields), 8-deep D chunk.
// ---------------------------------------------------------------------------
__device__ __forceinline__ float cc1(float si, float sj, float si2, float sj2, float sij) {
    const float inv = 1.0f / 729.0f;
    float cross = sij - si * sj * inv;
    float ivar  = si2 - si * si * inv;
    float jvar  = sj2 - sj * sj * inv;
    return __fdividef(cross * cross, ivar * jvar + 1e-5f);
}

__global__ void __launch_bounds__(256) dpass(float* __restrict__ out) {
    const int tid = threadIdx.x;
    const int col = blockIdx.x * 256 + tid;      // 0..10751 uint2 within plane
    const int d0  = blockIdx.y * 8;
    const uint2* B = (const uint2*)g_B;

    __half2 z2 = __float2half2_rn(0.f);
    __half2 aI0=z2, aI1=z2, aJ0=z2, aJ1=z2, aI20=z2, aI21=z2,
            aJ20=z2, aJ21=z2, aIJ0=z2, aIJ1=z2;

#define TAP(dp, HOP) { \
    size_t q = (size_t)(dp) * PL2 + col; \
    U2H4 v0, v1, v2, v3, v4; \
    v0.u = B[0u*VU2 + q]; v1.u = B[1u*VU2 + q]; v2.u = B[2u*VU2 + q]; \
    v3.u = B[3u*VU2 + q]; v4.u = B[4u*VU2 + q]; \
    aI0  = HOP(aI0,  v0.h[0]); aI1  = HOP(aI1,  v0.h[1]); \
    aJ0  = HOP(aJ0,  v1.h[0]); aJ1  = HOP(aJ1,  v1.h[1]); \
    aI20 = HOP(aI20, v2.h[0]); aI21 = HOP(aI21, v2.h[1]); \
    aJ20 = HOP(aJ20, v3.h[0]); aJ21 = HOP(aJ21, v3.h[1]); \
    aIJ0 = HOP(aIJ0, v4.h[0]); aIJ1 = HOP(aIJ1, v4.h[1]); }

#pragma unroll
    for (int t = -4; t <= 4; t++) {
        int dt = d0 + t;                          // d0+4 <= 156 < 160 always
        if (dt >= 0) TAP(dt, __hadd2);
    }

    float acc = 0.f;
#pragma unroll
    for (int dd = 0; dd < 8; dd++) {
        {
            float2 fI0 = __half22float2(aI0),  fI1 = __half22float2(aI1);
            float2 fJ0 = __half22float2(aJ0),  fJ1 = __half22float2(aJ1);
            float2 fA0 = __half22float2(aI20), fA1 = __half22float2(aI21);
            float2 fB0 = __half22float2(aJ20), fB1 = __half22float2(aJ21);
            float2 fC0 = __half22float2(aIJ0), fC1 = __half22float2(aIJ1);
            acc += cc1(fI0.x, fJ0.x, fA0.x, fB0.x, fC0.x);
            acc += cc1(fI0.y, fJ0.y, fA0.y, fB0.y, fC0.y);
            acc += cc1(fI1.x, fJ1.x, fA1.x, fB1.x, fC1.x);
            acc += cc1(fI1.y, fJ1.y, fA1.y, fB1.y, fC1.y);
        }
        int d = d0 + dd;
        int ta = d + 5, ts = d - 4;
        if (ta < DD) TAP(ta, __hadd2);
        if (ts >= 0) TAP(ts, __hsub2);
    }
#undef TAP

    // block reduction
#pragma unroll
    for (int o = 16; o > 0; o >>= 1) acc += __shfl_xor_sync(0xFFFFFFFFu, acc, o);
    __shared__ float wsum[8];
    if ((tid & 31) == 0) wsum[tid >> 5] = acc;
    __syncthreads();
    if (tid == 0) {
        float s = 0.f;
#pragma unroll
        for (int i = 0; i < 8; i++) s += wsum[i];
        atomicAdd(out, -s * (1.0f / (float)VV));
    }
}

// ---------------------------------------------------------------------------
extern "C" void kernel_launch(void* const* d_in, const int* in_sizes, int n_in,
                              void* d_out, int out_size) {
    const float* I = (const float*)d_in[0];
    const float* J = (const float*)d_in[1];
    float* out = (float*)d_out;

    wpass<<<7680, dim3(56, 4)>>>(I, J, out);   // 30720 rows / 4 (+ out init)
    hpass<<<dim3(35, 5, 8), 256>>>();          // 8960 cols, 5 fields, 8 H-chunks
    dpass<<<dim3(42, 20), 256>>>(out);         // 10752 u2-cols / 256, 20 D-chunks
}

// round 5
// speedup vs baseline: 2.4082x; 1.1924x over previous
#include <cuda_runtime.h>
#include <cuda_fp16.h>

#define DD 160
#define HH 192
#define WW 224
#define VV (DD*HH*WW)        // 6881280
#define W4 (WW/4)            // 56 float4 per input row
#define WU2 (WW/4)           // 56 uint2 (4-half) per row
#define VU2 (VV/4)           // uint2 elems per field
#define PL2 (HH*WW/4)        // uint2 per d-plane = 10752

#define WC 56                // W outputs per block
#define HC 32                // H outputs per block
#define RH 40                // raw rows (HC + 8)
#define RST 65               // raw smem stride (floats), odd -> conflict-free
#define SST 15               // summed smem stride (uint2 per row)

// fp16 scratch: 5 fields x VV halves (68.8 MB) — WH-summed fields
__device__ __half g_B[5u * VV];

union U2H4 { uint2 u; __half2 h[2]; };

// ---------------------------------------------------------------------------
// Fused pass 1+2: W-sum then H-sum of {I, J, I2, J2, IJ}, fp32 in, fp16 out.
// Block = 56(W) x 32(H) output tile at fixed d. 3 smem phases.
// ---------------------------------------------------------------------------
__global__ void __launch_bounds__(256) whpass(const float* __restrict__ I,
                                              const float* __restrict__ J,
                                              float* __restrict__ out) {
    __shared__ float sI[RH * RST];          // 10.4 KB
    __shared__ float sJ[RH * RST];          // 10.4 KB
    __shared__ uint2 sS[5 * RH * SST];      // 24 KB  (5 fields, 14 u2 used/row)

    const int tid = threadIdx.x;
    const int w0  = blockIdx.x * WC;
    const int h0  = blockIdx.y * HC;
    const int d   = blockIdx.z;
    if (blockIdx.x == 0 && blockIdx.y == 0 && blockIdx.z == 0 && tid == 0)
        out[0] = 0.f;

    // ---- phase 0: load raw I,J tile rows [h0-4, h0+36), w [w0-4, w0+60) ----
    const int fb = (w0 - 4) >> 2;           // first float4 index (may be -1)
    const float4* I4 = (const float4*)I;
    const float4* J4 = (const float4*)J;
    for (int i = tid; i < RH * 16; i += 256) {
        const int r = i >> 4, c = i & 15;
        const int gh = h0 - 4 + r;
        const int gf = fb + c;
        float4 a = make_float4(0.f, 0.f, 0.f, 0.f);
        float4 b = a;
        if (gh >= 0 && gh < HH && gf >= 0 && gf < W4) {
            const size_t q = ((size_t)d * HH + gh) * W4 + gf;
            a = I4[q]; b = J4[q];
        }
        const int s = r * RST + 4 * c;
        sI[s] = a.x; sI[s+1] = a.y; sI[s+2] = a.z; sI[s+3] = a.w;
        sJ[s] = b.x; sJ[s+1] = b.y; sJ[s+2] = b.z; sJ[s+3] = b.w;
    }
    __syncthreads();

    // ---- phase 1: W-sums (sliding 9-tap), 4 outputs/item, 5 fields -> sS ----
    for (int i = tid; i < 14 * RH; i += 256) {
        const int g = i / RH;              // output float4-group 0..13
        const int r = i - g * RH;          // row 0..39  (consecutive tids -> r)
        const int base = r * RST + 4 * g;  // tap t at base+t, t=0..11

        float iv[12], jv[12];
#pragma unroll
        for (int t = 0; t < 12; t++) { iv[t] = sI[base + t]; jv[t] = sJ[base + t]; }

        float oi[4], oj[4], oi2[4], oj2[4], oij[4];
        float si=0.f, sj=0.f, si2=0.f, sj2=0.f, sij=0.f;
#pragma unroll
        for (int t = 0; t < 9; t++) {
            float x = iv[t], y = jv[t];
            si += x; sj += y; si2 += x*x; sj2 += y*y; sij += x*y;
        }
        oi[0]=si; oj[0]=sj; oi2[0]=si2; oj2[0]=sj2; oij[0]=sij;
#pragma unroll
        for (int k = 1; k < 4; k++) {
            float ia = iv[k+8], ir = iv[k-1];
            float ja = jv[k+8], jr = jv[k-1];
            si  += ia - ir;        sj  += ja - jr;
            si2 += ia*ia - ir*ir;  sj2 += ja*ja - jr*jr;
            sij += ia*ja - ir*jr;
            oi[k]=si; oj[k]=sj; oi2[k]=si2; oj2[k]=sj2; oij[k]=sij;
        }

        const int so = r * SST + g;
        U2H4 t0, t1, t2, t3, t4;
        t0.h[0]=__floats2half2_rn(oi[0],oi[1]);   t0.h[1]=__floats2half2_rn(oi[2],oi[3]);
        t1.h[0]=__floats2half2_rn(oj[0],oj[1]);   t1.h[1]=__floats2half2_rn(oj[2],oj[3]);
        t2.h[0]=__floats2half2_rn(oi2[0],oi2[1]); t2.h[1]=__floats2half2_rn(oi2[2],oi2[3]);
        t3.h[0]=__floats2half2_rn(oj2[0],oj2[1]); t3.h[1]=__floats2half2_rn(oj2[2],oj2[3]);
        t4.h[0]=__floats2half2_rn(oij[0],oij[1]); t4.h[1]=__floats2half2_rn(oij[2],oij[3]);
        sS[0*RH*SST + so] = t0.u;
        sS[1*RH*SST + so] = t1.u;
        sS[2*RH*SST + so] = t2.u;
        sS[3*RH*SST + so] = t3.u;
        sS[4*RH*SST + so] = t4.u;
    }
    __syncthreads();

    // ---- phase 2: H-sums (running window over sS rows) -> g_B --------------
    if (tid < 224) {
        const int col  = tid % 14;          // uint2 column in tile
        const int rest = tid / 14;          // 0..15
        const int seg  = rest & 7;          // 4-row segment
        const int grp  = rest >> 3;         // 0: fields 0-2, 1: fields 3-4
        const int f0 = grp ? 3 : 0;
        const int f1 = grp ? 5 : 3;
        const int o0 = seg * 4;             // local output row base

        uint2* Bg = (uint2*)g_B;
        for (int f = f0; f < f1; f++) {
            const uint2* sf = &sS[f * RH * SST];
            __half2 s0 = __float2half2_rn(0.f), s1 = s0;
#pragma unroll
            for (int t = 0; t < 9; t++) {        // taps lr = o0 .. o0+8
                U2H4 v; v.u = sf[(o0 + t) * SST + col];
                s0 = __hadd2(s0, v.h[0]); s1 = __hadd2(s1, v.h[1]);
            }
            const size_t fbase = (size_t)f * VU2 + blockIdx.x * 14 + col;
#pragma unroll
            for (int k = 0; k < 4; k++) {
                U2H4 o; o.h[0] = s0; o.h[1] = s1;
                Bg[fbase + ((size_t)d * HH + h0 + o0 + k) * WU2] = o.u;
                if (k < 3) {
                    U2H4 va, vs;
                    va.u = sf[(o0 + k + 9) * SST + col];
                    vs.u = sf[(o0 + k) * SST + col];
                    s0 = __hadd2(__hsub2(s0, vs.h[0]), va.h[0]);
                    s1 = __hadd2(__hsub2(s1, vs.h[1]), va.h[1]);
                }
            }
        }
    }
}

// ---------------------------------------------------------------------------
// Pass 3: along D. fp16 running-window accumulators; fp32 only at cc time.
// ---------------------------------------------------------------------------
__device__ __forceinline__ float cc1(float si, float sj, float si2, float sj2, float sij) {
    const float inv = 1.0f / 729.0f;
    float cross = sij - si * sj * inv;
    float ivar  = si2 - si * si * inv;
    float jvar  = sj2 - sj * sj * inv;
    return __fdividef(cross * cross, ivar * jvar + 1e-5f);
}

__global__ void __launch_bounds__(256) dpass(float* __restrict__ out) {
    const int tid = threadIdx.x;
    const int col = blockIdx.x * 256 + tid;      // uint2 index within plane
    const int d0  = blockIdx.y * 8;
    const uint2* B = (const uint2*)g_B;

    __half2 z2 = __float2half2_rn(0.f);
    __half2 aI0=z2, aI1=z2, aJ0=z2, aJ1=z2, aI20=z2, aI21=z2,
            aJ20=z2, aJ21=z2, aIJ0=z2, aIJ1=z2;

#define TAP(dp, HOP) { \
    size_t q = (size_t)(dp) * PL2 + col; \
    U2H4 v0, v1, v2, v3, v4; \
    v0.u = B[0u*VU2 + q]; v1.u = B[1u*VU2 + q]; v2.u = B[2u*VU2 + q]; \
    v3.u = B[3u*VU2 + q]; v4.u = B[4u*VU2 + q]; \
    aI0  = HOP(aI0,  v0.h[0]); aI1  = HOP(aI1,  v0.h[1]); \
    aJ0  = HOP(aJ0,  v1.h[0]); aJ1  = HOP(aJ1,  v1.h[1]); \
    aI20 = HOP(aI20, v2.h[0]); aI21 = HOP(aI21, v2.h[1]); \
    aJ20 = HOP(aJ20, v3.h[0]); aJ21 = HOP(aJ21, v3.h[1]); \
    aIJ0 = HOP(aIJ0, v4.h[0]); aIJ1 = HOP(aIJ1, v4.h[1]); }

#pragma unroll
    for (int t = -4; t <= 4; t++) {
        int dt = d0 + t;                          // d0+4 <= 156 < 160 always
        if (dt >= 0) TAP(dt, __hadd2);
    }

    float acc = 0.f;
#pragma unroll
    for (int dd = 0; dd < 8; dd++) {
        {
            float2 fI0 = __half22float2(aI0),  fI1 = __half22float2(aI1);
            float2 fJ0 = __half22float2(aJ0),  fJ1 = __half22float2(aJ1);
            float2 fA0 = __half22float2(aI20), fA1 = __half22float2(aI21);
            float2 fB0 = __half22float2(aJ20), fB1 = __half22float2(aJ21);
            float2 fC0 = __half22float2(aIJ0), fC1 = __half22float2(aIJ1);
            acc += cc1(fI0.x, fJ0.x, fA0.x, fB0.x, fC0.x);
            acc += cc1(fI0.y, fJ0.y, fA0.y, fB0.y, fC0.y);
            acc += cc1(fI1.x, fJ1.x, fA1.x, fB1.x, fC1.x);
            acc += cc1(fI1.y, fJ1.y, fA1.y, fB1.y, fC1.y);
        }
        int d = d0 + dd;
        int ta = d + 5, ts = d - 4;
        if (ta < DD) TAP(ta, __hadd2);
        if (ts >= 0) TAP(ts, __hsub2);
    }
#undef TAP

    // block reduction
#pragma unroll
    for (int o = 16; o > 0; o >>= 1) acc += __shfl_xor_sync(0xFFFFFFFFu, acc, o);
    __shared__ float wsum[8];
    if ((tid & 31) == 0) wsum[tid >> 5] = acc;
    __syncthreads();
    if (tid == 0) {
        float s = 0.f;
#pragma unroll
        for (int i = 0; i < 8; i++) s += wsum[i];
        atomicAdd(out, -s * (1.0f / (float)VV));
    }
}

// ---------------------------------------------------------------------------
extern "C" void kernel_launch(void* const* d_in, const int* in_sizes, int n_in,
                              void* d_out, int out_size) {
    const float* I = (const float*)d_in[0];
    const float* J = (const float*)d_in[1];
    float* out = (float*)d_out;

    whpass<<<dim3(4, 6, DD), 256>>>(I, J, out);  // 4 W-chunks x 6 H-chunks x 160 d
    dpass<<<dim3(42, 20), 256>>>(out);           // 10752 u2-cols / 256, 20 D-chunks
}